// round 9
// baseline (speedup 1.0000x reference)
#include <cuda_runtime.h>
#include <cstdint>
#include <cstddef>

#define DI __device__ __forceinline__

namespace {
constexpr int IN_DIM  = 1024;
constexpr int MEM_DIM = 512;
constexpr int N_NODES = 100000;
constexpr int BATCH   = 65536;

constexpr int BM = 128, BN = 256, BK = 32;
constexpr int MT = BATCH / BM;     // 512
constexpr int NT = MEM_DIM / BN;   // 2
constexpr int KC = IN_DIM / BK;    // 32
constexpr int THREADS = 256;       // 8 warps: 2 (M) x 4 (N), warp tile 64x64
constexpr int STAGES = 4;

// smem per stage: A[128 rows][128B] + B[256 rows][128B]; a row = 32 fp32 (one BK chunk),
// 16B units XOR-swizzled by (row&7) for conflict-free ldmatrix.
constexpr int SA_BYTES    = BM * 128;               // 16 KB
constexpr int SB_BYTES    = BN * 128;               // 32 KB
constexpr int STAGE_BYTES = SA_BYTES + SB_BYTES;    // 48 KB
constexpr int SMEM_BYTES  = STAGES * STAGE_BYTES;   // 192 KB
}  // namespace

// ---------------- base-ISA helpers (NO tcgen05 — target is plain sm_103) ----------------

DI uint32_t smem_u32(const void* p) {
    uint32_t a;
    asm("{ .reg .u64 t; cvta.to.shared.u64 t, %1; cvt.u32.u64 %0, t; }" : "=r"(a) : "l"(p));
    return a;
}

DI uint32_t f2tf32(uint32_t fbits) {   // round-to-nearest tf32 on raw fp32 bits
    uint32_t r;
    asm("cvt.rna.tf32.f32 %0, %1;" : "=r"(r) : "r"(fbits));
    return r;
}

DI void ldsm_x4(uint32_t* r, uint32_t addr) {
    asm volatile("ldmatrix.sync.aligned.m8n8.x4.shared.b16 {%0,%1,%2,%3}, [%4];"
                 : "=r"(r[0]), "=r"(r[1]), "=r"(r[2]), "=r"(r[3]) : "r"(addr));
}

DI void mma_tf32(float* c, const uint32_t* a, const uint32_t* b) {
    asm volatile(
        "mma.sync.aligned.m16n8k8.row.col.f32.tf32.tf32.f32 "
        "{%0,%1,%2,%3}, {%4,%5,%6,%7}, {%8,%9}, {%0,%1,%2,%3};"
        : "+f"(c[0]), "+f"(c[1]), "+f"(c[2]), "+f"(c[3])
        : "r"(a[0]), "r"(a[1]), "r"(a[2]), "r"(a[3]), "r"(b[0]), "r"(b[1]));
}

DI void cp_async16(uint32_t smem_addr, const void* gptr) {
    asm volatile("cp.async.cg.shared.global [%0], [%1], 16;"
                 :: "r"(smem_addr), "l"(gptr));
}
DI void cp_commit() { asm volatile("cp.async.commit_group;"); }
DI void cp_wait1()  { asm volatile("cp.async.wait_group 1;"); }

// ---------------- Kernel 1: out = concat(entity_mem, rel_mem) * (t>1 ? t/(t+1) : 1) ----------------

__global__ void init_out_kernel(const float4* __restrict__ ent, const float4* __restrict__ rel,
                                const int* __restrict__ timep, float4* __restrict__ out) {
    const long long NODE4 = (long long)N_NODES * MEM_DIM / 4;
    const long long TOT4  = NODE4 + 500LL * MEM_DIM / 4;
    long long i = (long long)blockIdx.x * blockDim.x + threadIdx.x;
    if (i >= TOT4) return;
    int t = *timep;
    float s = (t > 1) ? (float)t / (float)(t + 1) : 1.0f;
    float4 v = (i < NODE4) ? ent[i] : rel[i - NODE4];
    v.x *= s; v.y *= s; v.z *= s; v.w *= s;
    out[i] = v;
}

// ---------------- Kernel 2: TF32 mma.sync GEMM, cp.async 4-stage + kstep software pipeline ----------------

__global__ void __launch_bounds__(THREADS, 1)
gemm_scatter_kernel(const float* __restrict__ nodes_emb, const float* __restrict__ rels_emb,
                    const int* __restrict__ nodes_ids, const int* __restrict__ rels_ids,
                    const float* __restrict__ W_node, const float* __restrict__ b_node,
                    const float* __restrict__ W_rel, const float* __restrict__ b_rel,
                    const int* __restrict__ timep, float* __restrict__ out) {
    extern __shared__ char smem[];
    const uint32_t sb = smem_u32(smem);
    const int tid = threadIdx.x;
    const int lane = tid & 31;
    const int wid = tid >> 5;
    const int wm = wid & 1;      // warp row (2)  -> 64 M rows each
    const int wn = wid >> 1;     // warp col (4)  -> 64 N cols each

    const bool is_rel = (blockIdx.x >= (unsigned)(MT * NT));
    const int bid = is_rel ? (int)blockIdx.x - MT * NT : (int)blockIdx.x;
    const int tile_n = bid & (NT - 1);
    const int tile_m = bid >> 1;

    const float* Aptr = is_rel ? rels_emb : nodes_emb;
    const float* Wptr = is_rel ? W_rel : W_node;
    const float* bias = is_rel ? b_rel : b_node;
    const int*   ids  = is_rel ? rels_ids : nodes_ids;
    float* outhalf = out + (is_rel ? (size_t)N_NODES * MEM_DIM : 0);

    const float* Abase = Aptr + (size_t)(tile_m * BM) * IN_DIM;
    const float* Wbase = Wptr + (size_t)(tile_n * BN) * IN_DIM;

    // ---- cp.async slots: arithmetic progressions from a single (go0, st0) pair ----
    // slot j covers rows (tid>>3) + 32*j; (row & 7) is j-invariant -> swizzle term constant.
    const uint32_t go0 = (uint32_t)((tid >> 3) * IN_DIM + (tid & 7) * 4);            // element offset
    const uint32_t st0 = (uint32_t)((tid >> 3) * 128 + (((tid & 7) ^ ((tid >> 3) & 7)) << 4));

    auto issue_chunk = [&](int kc) {   // always commits (uniform wait arithmetic)
        if (kc < KC) {
            const uint32_t go = go0 + (uint32_t)(kc * BK);
            const uint32_t stg = sb + (uint32_t)((kc & (STAGES - 1)) * STAGE_BYTES);
#pragma unroll
            for (int j = 0; j < 4; ++j)                 // A: 4 slots, stride 32 rows
                cp_async16(stg + st0 + j * 32 * 128, Abase + go + j * 32 * IN_DIM);
#pragma unroll
            for (int j = 0; j < 8; ++j)                 // B: 8 slots
                cp_async16(stg + SA_BYTES + st0 + j * 32 * 128, Wbase + go + j * 32 * IN_DIM);
        }
        cp_commit();
    };

    // ---- ldmatrix addressing: scalar base + compile-time strides; XOR term is mt/np-invariant ----
    const int a_khi = lane >> 4;
    const int arow0 = wm * 64 + (lane & 7) + ((lane >> 3) & 1) * 8;   // + mt*16 (16 = 0 mod 8)
    const uint32_t a_rb = (uint32_t)(arow0 * 128);
    const int a_r7 = arow0 & 7;
    const int b_khi = (lane >> 3) & 1;
    const int brow0 = wn * 64 + (lane & 7) + ((lane >> 4) & 1) * 8;
    const uint32_t b_rb = (uint32_t)(SA_BYTES + brow0 * 128);
    const int b_r7 = brow0 & 7;

    // fragment double buffers (parity = kstep & 1)
    uint32_t Af[2][16], Bf[2][16];

    auto load_frags = [&](uint32_t* A, uint32_t* B, uint32_t stage, int ks) {
        const uint32_t aoff = stage + a_rb + (uint32_t)(((2 * ks + a_khi) ^ a_r7) << 4);
        const uint32_t boff = stage + b_rb + (uint32_t)(((2 * ks + b_khi) ^ b_r7) << 4);
#pragma unroll
        for (int mt = 0; mt < 4; ++mt) {
            ldsm_x4(A + mt * 4, aoff + mt * 2048);      // 16 rows * 128B
#pragma unroll
            for (int v = 0; v < 4; ++v) A[mt * 4 + v] = f2tf32(A[mt * 4 + v]);
        }
#pragma unroll
        for (int np = 0; np < 4; ++np) {
            ldsm_x4(B + np * 4, boff + np * 2048);
#pragma unroll
            for (int v = 0; v < 4; ++v) B[np * 4 + v] = f2tf32(B[np * 4 + v]);
        }
    };

    float C[4][8][4];
#pragma unroll
    for (int mt = 0; mt < 4; ++mt)
#pragma unroll
        for (int nt = 0; nt < 8; ++nt)
#pragma unroll
            for (int v = 0; v < 4; ++v) C[mt][nt][v] = 0.0f;

    // ---- prologue: 3 chunks in flight; preload (chunk0, ks0) fragments ----
    issue_chunk(0);
    issue_chunk(1);
    issue_chunk(2);
    cp_wait1();          // groups 0,1 complete
    __syncthreads();
    load_frags(Af[0], Bf[0], sb, 0);

    // ---- main loop: per chunk [wait1, sync, issue(kc+3)]; ksteps pipelined incl. cross-chunk ----
    for (int kc = 0; kc < KC; ++kc) {
        cp_wait1();          // 0..kc+1 complete  (issued so far: 0..kc+2)
        __syncthreads();     // all warps past stage (kc-1) reads
        issue_chunk(kc + 3); // writes stage (kc-1)%4 -- safe after the barrier

        const uint32_t cur = sb + (uint32_t)((kc & (STAGES - 1)) * STAGE_BYTES);
        const uint32_t nxt = sb + (uint32_t)(((kc + 1) & (STAGES - 1)) * STAGE_BYTES);
#pragma unroll
        for (int ks = 0; ks < 4; ++ks) {
            const int cb = ks & 1, nb = cb ^ 1;
            if (ks < 3) {
                load_frags(Af[nb], Bf[nb], cur, ks + 1);
            } else if (kc + 1 < KC) {
                load_frags(Af[nb], Bf[nb], nxt, 0);     // stage kc+1 is complete (wait1 above)
            }
            // 32 independent mmas overlap the fragment loads above
#pragma unroll
            for (int np = 0; np < 4; ++np)
#pragma unroll
                for (int mt = 0; mt < 4; ++mt) {
                    mma_tf32(C[mt][2 * np],     Af[cb] + mt * 4, Bf[cb] + np * 4);
                    mma_tf32(C[mt][2 * np + 1], Af[cb] + mt * 4, Bf[cb] + np * 4 + 2);
                }
        }
    }

    // ---- epilogue: out[id[m]] += (C + bias) / (t+1), atomic (RED) scatter ----
    const int t = *timep;
    const float inv = 1.0f / (float)(t + 1);
    const int g = lane >> 2;
    const int tg = lane & 3;

    float* p[8];
#pragma unroll
    for (int mt = 0; mt < 4; ++mt) {
        int r0 = tile_m * BM + wm * 64 + mt * 16 + g;
        p[2 * mt]     = outhalf + (size_t)ids[r0] * MEM_DIM;
        p[2 * mt + 1] = outhalf + (size_t)ids[r0 + 8] * MEM_DIM;
    }
#pragma unroll
    for (int nt = 0; nt < 8; ++nt) {
        const int c = tile_n * BN + wn * 64 + nt * 8 + tg * 2;
        const float2 bv = *reinterpret_cast<const float2*>(bias + c);
#pragma unroll
        for (int mt = 0; mt < 4; ++mt) {
            atomicAdd(p[2 * mt] + c,         (C[mt][nt][0] + bv.x) * inv);
            atomicAdd(p[2 * mt] + c + 1,     (C[mt][nt][1] + bv.y) * inv);
            atomicAdd(p[2 * mt + 1] + c,     (C[mt][nt][2] + bv.x) * inv);
            atomicAdd(p[2 * mt + 1] + c + 1, (C[mt][nt][3] + bv.y) * inv);
        }
    }
}

// ---------------- launch ----------------

extern "C" void kernel_launch(void* const* d_in, const int* in_sizes, int n_in,
                              void* d_out, int out_size) {
    const float* nodes_emb = (const float*)d_in[0];
    const float* rels_emb  = (const float*)d_in[1];
    const int*   nodes_ids = (const int*)d_in[2];
    const int*   rels_ids  = (const int*)d_in[3];
    const float* ent_mem   = (const float*)d_in[4];
    const float* rel_mem   = (const float*)d_in[5];
    const float* W_node    = (const float*)d_in[6];
    const float* b_node    = (const float*)d_in[7];
    const float* W_rel     = (const float*)d_in[8];
    const float* b_rel     = (const float*)d_in[9];
    const int*   timep     = (const int*)d_in[10];
    float* out = (float*)d_out;

    static bool attr_set = false;
    if (!attr_set) {
        cudaFuncSetAttribute(gemm_scatter_kernel,
                             cudaFuncAttributeMaxDynamicSharedMemorySize, SMEM_BYTES);
        attr_set = true;
    }

    // 1) out = scaled concat of memories
    const long long TOT4 = ((long long)N_NODES * MEM_DIM + 500LL * MEM_DIM) / 4;
    const int blocks = (int)((TOT4 + 255) / 256);
    init_out_kernel<<<blocks, 256>>>((const float4*)ent_mem, (const float4*)rel_mem, timep,
                                     (float4*)out);

    // 2) TF32 GEMM + scatter: nodes half then rels half in one grid
    gemm_scatter_kernel<<<2 * MT * NT, THREADS, SMEM_BYTES>>>(
        nodes_emb, rels_emb, nodes_ids, rels_ids,
        W_node, b_node, W_rel, b_rel, timep, out);
}

// round 10
// speedup vs baseline: 1.1116x; 1.1116x over previous
#include <cuda_runtime.h>
#include <cstdint>
#include <cstddef>

#define DI __device__ __forceinline__

namespace {
constexpr int IN_DIM  = 1024;
constexpr int MEM_DIM = 512;
constexpr int N_NODES = 100000;
constexpr int BATCH   = 65536;

constexpr int BM = 128, BN = 256, BK = 32;
constexpr int MT = BATCH / BM;     // 512
constexpr int NT = MEM_DIM / BN;   // 2
constexpr int KC = IN_DIM / BK;    // 32
constexpr int THREADS = 256;       // 8 warps: 2 (M) x 4 (N), warp tile 64x64
constexpr int STAGES = 4;

// smem per stage: A[128 rows][128B] + B[256 rows][128B]; a row = 32 fp32 (one BK chunk),
// 16B units XOR-swizzled by (row&7) for conflict-free ldmatrix.
constexpr int SA_BYTES    = BM * 128;               // 16 KB
constexpr int SB_BYTES    = BN * 128;               // 32 KB
constexpr int STAGE_BYTES = SA_BYTES + SB_BYTES;    // 48 KB
constexpr int SMEM_BYTES  = STAGES * STAGE_BYTES;   // 192 KB
}  // namespace

// ---------------- base-ISA helpers (NO tcgen05 — target is plain sm_103) ----------------

DI uint32_t smem_u32(const void* p) {
    uint32_t a;
    asm("{ .reg .u64 t; cvta.to.shared.u64 t, %1; cvt.u32.u64 %0, t; }" : "=r"(a) : "l"(p));
    return a;
}

DI uint32_t f2tf32(uint32_t fbits) {   // round-to-nearest tf32 on raw fp32 bits
    uint32_t r;
    asm("cvt.rna.tf32.f32 %0, %1;" : "=r"(r) : "r"(fbits));
    return r;
}

DI void ldsm_x4(uint32_t* r, uint32_t addr) {
    asm volatile("ldmatrix.sync.aligned.m8n8.x4.shared.b16 {%0,%1,%2,%3}, [%4];"
                 : "=r"(r[0]), "=r"(r[1]), "=r"(r[2]), "=r"(r[3]) : "r"(addr));
}

DI void cvt4(uint32_t* r) {
#pragma unroll
    for (int v = 0; v < 4; ++v) r[v] = f2tf32(r[v]);
}

DI void mma_tf32(float* c, const uint32_t* a, const uint32_t* b) {
    asm volatile(
        "mma.sync.aligned.m16n8k8.row.col.f32.tf32.tf32.f32 "
        "{%0,%1,%2,%3}, {%4,%5,%6,%7}, {%8,%9}, {%0,%1,%2,%3};"
        : "+f"(c[0]), "+f"(c[1]), "+f"(c[2]), "+f"(c[3])
        : "r"(a[0]), "r"(a[1]), "r"(a[2]), "r"(a[3]), "r"(b[0]), "r"(b[1]));
}

DI void cp_async16(uint32_t smem_addr, const void* gptr) {
    asm volatile("cp.async.cg.shared.global [%0], [%1], 16;"
                 :: "r"(smem_addr), "l"(gptr));
}
DI void cp_commit() { asm volatile("cp.async.commit_group;"); }
DI void cp_wait1()  { asm volatile("cp.async.wait_group 1;"); }

// ---------------- Kernel 1: out = concat(entity_mem, rel_mem) * (t>1 ? t/(t+1) : 1) ----------------

__global__ void init_out_kernel(const float4* __restrict__ ent, const float4* __restrict__ rel,
                                const int* __restrict__ timep, float4* __restrict__ out) {
    const long long NODE4 = (long long)N_NODES * MEM_DIM / 4;
    const long long TOT4  = NODE4 + 500LL * MEM_DIM / 4;
    long long i = (long long)blockIdx.x * blockDim.x + threadIdx.x;
    if (i >= TOT4) return;
    int t = *timep;
    float s = (t > 1) ? (float)t / (float)(t + 1) : 1.0f;
    float4 v = (i < NODE4) ? ent[i] : rel[i - NODE4];
    v.x *= s; v.y *= s; v.z *= s; v.w *= s;
    out[i] = v;
}

// ---------------- Kernel 2: TF32 mma.sync GEMM, cp.async 4-stage, rolling fragment pipeline ----------------

__global__ void __launch_bounds__(THREADS, 1)
gemm_scatter_kernel(const float* __restrict__ nodes_emb, const float* __restrict__ rels_emb,
                    const int* __restrict__ nodes_ids, const int* __restrict__ rels_ids,
                    const float* __restrict__ W_node, const float* __restrict__ b_node,
                    const float* __restrict__ W_rel, const float* __restrict__ b_rel,
                    const int* __restrict__ timep, float* __restrict__ out) {
    extern __shared__ char smem[];
    const uint32_t sb = smem_u32(smem);
    const int tid = threadIdx.x;
    const int lane = tid & 31;
    const int wid = tid >> 5;
    const int wm = wid & 1;      // warp row (2)  -> 64 M rows each
    const int wn = wid >> 1;     // warp col (4)  -> 64 N cols each

    const bool is_rel = (blockIdx.x >= (unsigned)(MT * NT));
    const int bid = is_rel ? (int)blockIdx.x - MT * NT : (int)blockIdx.x;
    const int tile_n = bid & (NT - 1);
    const int tile_m = bid >> 1;

    const float* Aptr = is_rel ? rels_emb : nodes_emb;
    const float* Wptr = is_rel ? W_rel : W_node;
    const float* bias = is_rel ? b_rel : b_node;
    const int*   ids  = is_rel ? rels_ids : nodes_ids;
    float* outhalf = out + (is_rel ? (size_t)N_NODES * MEM_DIM : 0);

    const float* Abase = Aptr + (size_t)(tile_m * BM) * IN_DIM;
    const float* Wbase = Wptr + (size_t)(tile_n * BN) * IN_DIM;

    // ---- cp.async slots: arithmetic progressions from one (go0, st0) pair ----
    const uint32_t go0 = (uint32_t)((tid >> 3) * IN_DIM + (tid & 7) * 4);
    const uint32_t st0 = (uint32_t)((tid >> 3) * 128 + (((tid & 7) ^ ((tid >> 3) & 7)) << 4));

    auto issue_chunk = [&](int kc) {   // always commits (uniform wait arithmetic)
        if (kc < KC) {
            const uint32_t go = go0 + (uint32_t)(kc * BK);
            const uint32_t stg = sb + (uint32_t)((kc & (STAGES - 1)) * STAGE_BYTES);
#pragma unroll
            for (int j = 0; j < 4; ++j)
                cp_async16(stg + st0 + j * 32 * 128, Abase + go + j * 32 * IN_DIM);
#pragma unroll
            for (int j = 0; j < 8; ++j)
                cp_async16(stg + SA_BYTES + st0 + j * 32 * 128, Wbase + go + j * 32 * IN_DIM);
        }
        cp_commit();
    };

    // ---- ldmatrix addressing: scalar bases; XOR swizzle term is mt/np-invariant ----
    const int a_khi = lane >> 4;
    const int arow0 = wm * 64 + (lane & 7) + ((lane >> 3) & 1) * 8;   // + mt*16 (0 mod 8)
    const uint32_t a_rb = (uint32_t)(arow0 * 128);
    const int a_r7 = arow0 & 7;
    const int b_khi = (lane >> 3) & 1;
    const int brow0 = wn * 64 + (lane & 7) + ((lane >> 4) & 1) * 8;
    const uint32_t b_rb = (uint32_t)(SA_BYTES + brow0 * 128);
    const int b_r7 = brow0 & 7;

    // A: double-buffered per kstep (parity ks&1). B: rolling per np (parity np&1).
    uint32_t Af[2][16], Bf[2][4];

    auto load_A_half = [&](uint32_t* A, uint32_t aoff, int half) {
#pragma unroll
        for (int mt = 0; mt < 2; ++mt) {
            ldsm_x4(A + (half * 2 + mt) * 4, aoff + (half * 2 + mt) * 2048);
            cvt4(A + (half * 2 + mt) * 4);
        }
    };

    float C[4][8][4];
#pragma unroll
    for (int mt = 0; mt < 4; ++mt)
#pragma unroll
        for (int nt = 0; nt < 8; ++nt)
#pragma unroll
            for (int v = 0; v < 4; ++v) C[mt][nt][v] = 0.0f;

    // mma batch: 8 independent mmas for one (np) column block
    auto mma_batch = [&](int np, const uint32_t* A, const uint32_t* B) {
#pragma unroll
        for (int mt = 0; mt < 4; ++mt) {
            mma_tf32(C[mt][2 * np],     A + mt * 4, B);
            mma_tf32(C[mt][2 * np + 1], A + mt * 4, B + 2);
        }
    };

    // ---- prologue: 3 chunks in flight; preload (chunk0, ks0) A and (np0) B ----
    issue_chunk(0);
    issue_chunk(1);
    issue_chunk(2);
    cp_wait1();          // chunks 0,1 complete
    __syncthreads();
    {
        const uint32_t aoff = sb + a_rb + (uint32_t)((a_khi ^ a_r7) << 4);
        load_A_half(Af[0], aoff, 0);
        load_A_half(Af[0], aoff, 1);
        ldsm_x4(Bf[0], sb + b_rb + (uint32_t)((b_khi ^ b_r7) << 4));
        cvt4(Bf[0]);
    }

    // ---- main loop ----
    for (int kc = 0; kc < KC; ++kc) {
        cp_wait1();          // chunks 0..kc+1 complete (issued 0..kc+2)
        __syncthreads();     // all warps past stage (kc-1) reads
        issue_chunk(kc + 3); // writes stage (kc-1)%4 -- safe after the barrier

        const uint32_t cur = sb + (uint32_t)((kc & (STAGES - 1)) * STAGE_BYTES);
        const uint32_t nxt = sb + (uint32_t)(((kc + 1) & (STAGES - 1)) * STAGE_BYTES);
        const bool not_last_chunk = (kc + 1 < KC);

#pragma unroll
        for (int ks = 0; ks < 4; ++ks) {
            const int cb = ks & 1, nb = cb ^ 1;
            const bool lk = (ks == 3);
            const bool dn = (!lk) || not_last_chunk;       // is there a next kstep?
            const uint32_t nstage = lk ? nxt : cur;        // stage holding next kstep
            const int nks = lk ? 0 : ks + 1;

            const uint32_t boff_c = cur + b_rb + (uint32_t)(((2 * ks + b_khi) ^ b_r7) << 4);
            const uint32_t boff_n = nstage + b_rb + (uint32_t)(((2 * nks + b_khi) ^ b_r7) << 4);
            const uint32_t aoff_n = nstage + a_rb + (uint32_t)(((2 * nks + a_khi) ^ a_r7) << 4);

            // np=0: prefetch B(np1); mma np0
            ldsm_x4(Bf[1], boff_c + 1 * 2048); cvt4(Bf[1]);
            mma_batch(0, Af[cb], Bf[0]);
            // np=1: prefetch B(np2) + next-A half 0; mma np1
            ldsm_x4(Bf[0], boff_c + 2 * 2048); cvt4(Bf[0]);
            if (dn) load_A_half(Af[nb], aoff_n, 0);
            mma_batch(1, Af[cb], Bf[1]);
            // np=2: prefetch B(np3) + next-A half 1; mma np2
            ldsm_x4(Bf[1], boff_c + 3 * 2048); cvt4(Bf[1]);
            if (dn) load_A_half(Af[nb], aoff_n, 1);
            mma_batch(2, Af[cb], Bf[0]);
            // np=3: prefetch B(next kstep, np0); mma np3
            if (dn) { ldsm_x4(Bf[0], boff_n); cvt4(Bf[0]); }
            mma_batch(3, Af[cb], Bf[1]);
        }
    }

    // ---- epilogue: out[id[m]] += (C + bias) / (t+1), atomic (RED) scatter ----
    const int t = *timep;
    const float inv = 1.0f / (float)(t + 1);
    const int g = lane >> 2;
    const int tg = lane & 3;

    float* p[8];
#pragma unroll
    for (int mt = 0; mt < 4; ++mt) {
        int r0 = tile_m * BM + wm * 64 + mt * 16 + g;
        p[2 * mt]     = outhalf + (size_t)ids[r0] * MEM_DIM;
        p[2 * mt + 1] = outhalf + (size_t)ids[r0 + 8] * MEM_DIM;
    }
#pragma unroll
    for (int nt = 0; nt < 8; ++nt) {
        const int c = tile_n * BN + wn * 64 + nt * 8 + tg * 2;
        const float2 bv = *reinterpret_cast<const float2*>(bias + c);
#pragma unroll
        for (int mt = 0; mt < 4; ++mt) {
            atomicAdd(p[2 * mt] + c,         (C[mt][nt][0] + bv.x) * inv);
            atomicAdd(p[2 * mt] + c + 1,     (C[mt][nt][1] + bv.y) * inv);
            atomicAdd(p[2 * mt + 1] + c,     (C[mt][nt][2] + bv.x) * inv);
            atomicAdd(p[2 * mt + 1] + c + 1, (C[mt][nt][3] + bv.y) * inv);
        }
    }
}

// ---------------- launch ----------------

extern "C" void kernel_launch(void* const* d_in, const int* in_sizes, int n_in,
                              void* d_out, int out_size) {
    const float* nodes_emb = (const float*)d_in[0];
    const float* rels_emb  = (const float*)d_in[1];
    const int*   nodes_ids = (const int*)d_in[2];
    const int*   rels_ids  = (const int*)d_in[3];
    const float* ent_mem   = (const float*)d_in[4];
    const float* rel_mem   = (const float*)d_in[5];
    const float* W_node    = (const float*)d_in[6];
    const float* b_node    = (const float*)d_in[7];
    const float* W_rel     = (const float*)d_in[8];
    const float* b_rel     = (const float*)d_in[9];
    const int*   timep     = (const int*)d_in[10];
    float* out = (float*)d_out;

    static bool attr_set = false;
    if (!attr_set) {
        cudaFuncSetAttribute(gemm_scatter_kernel,
                             cudaFuncAttributeMaxDynamicSharedMemorySize, SMEM_BYTES);
        attr_set = true;
    }

    // 1) out = scaled concat of memories
    const long long TOT4 = ((long long)N_NODES * MEM_DIM + 500LL * MEM_DIM) / 4;
    const int blocks = (int)((TOT4 + 255) / 256);
    init_out_kernel<<<blocks, 256>>>((const float4*)ent_mem, (const float4*)rel_mem, timep,
                                     (float4*)out);

    // 2) TF32 GEMM + scatter: nodes half then rels half in one grid
    gemm_scatter_kernel<<<2 * MT * NT, THREADS, SMEM_BYTES>>>(
        nodes_emb, rels_emb, nodes_ids, rels_ids,
        W_node, b_node, W_rel, b_rel, timep, out);
}

// round 11
// speedup vs baseline: 1.6985x; 1.5280x over previous
#include <cuda_runtime.h>
#include <cstdint>
#include <cstddef>

#define DI __device__ __forceinline__

namespace {
constexpr int IN_DIM  = 1024;
constexpr int MEM_DIM = 512;
constexpr int N_NODES = 100000;
constexpr int BATCH   = 65536;

constexpr int BM = 128, BN = 256, BK = 32;
constexpr int MT = BATCH / BM;     // 512
constexpr int NT = MEM_DIM / BN;   // 2
constexpr int KC = IN_DIM / BK;    // 32
constexpr int THREADS = 256;       // 8 warps: 2 (M) x 4 (N), warp tile 64x64
constexpr int STAGES = 4;

// smem per stage: A[128 rows][128B] + B[256 rows][128B]; a row = 32 fp32 (one BK chunk),
// 16B units XOR-swizzled by (row&7) for conflict-free ldmatrix.
constexpr int SA_BYTES    = BM * 128;               // 16 KB
constexpr int SB_BYTES    = BN * 128;               // 32 KB
constexpr int STAGE_BYTES = SA_BYTES + SB_BYTES;    // 48 KB
constexpr int SMEM_BYTES  = STAGES * STAGE_BYTES;   // 192 KB
}  // namespace

// ---------------- base-ISA helpers (NO tcgen05 — target is plain sm_103) ----------------

DI uint32_t smem_u32(const void* p) {
    uint32_t a;
    asm("{ .reg .u64 t; cvta.to.shared.u64 t, %1; cvt.u32.u64 %0, t; }" : "=r"(a) : "l"(p));
    return a;
}

DI uint32_t f2tf32(uint32_t fbits) {   // round-to-nearest tf32 on raw fp32 bits
    uint32_t r;
    asm("cvt.rna.tf32.f32 %0, %1;" : "=r"(r) : "r"(fbits));
    return r;
}

DI void ldsm_x4(uint32_t* r, uint32_t addr) {
    asm volatile("ldmatrix.sync.aligned.m8n8.x4.shared.b16 {%0,%1,%2,%3}, [%4];"
                 : "=r"(r[0]), "=r"(r[1]), "=r"(r[2]), "=r"(r[3]) : "r"(addr));
}

DI void mma_tf32(float* c, const uint32_t* a, const uint32_t* b) {
    asm volatile(
        "mma.sync.aligned.m16n8k8.row.col.f32.tf32.tf32.f32 "
        "{%0,%1,%2,%3}, {%4,%5,%6,%7}, {%8,%9}, {%0,%1,%2,%3};"
        : "+f"(c[0]), "+f"(c[1]), "+f"(c[2]), "+f"(c[3])
        : "r"(a[0]), "r"(a[1]), "r"(a[2]), "r"(a[3]), "r"(b[0]), "r"(b[1]));
}

DI void cp_async16(uint32_t smem_addr, const void* gptr) {
    asm volatile("cp.async.cg.shared.global [%0], [%1], 16;"
                 :: "r"(smem_addr), "l"(gptr));
}
DI void cp_commit() { asm volatile("cp.async.commit_group;"); }
DI void cp_wait2()  { asm volatile("cp.async.wait_group 2;"); }

DI void red_add_v2(float* gaddr, float x, float y) {   // vector reduction, no return (sm_90+)
    asm volatile("red.global.add.v2.f32 [%0], {%1, %2};"
                 :: "l"(gaddr), "f"(x), "f"(y) : "memory");
}

// ---------------- Kernel 1: out = concat(entity_mem, rel_mem) * (t>1 ? t/(t+1) : 1) ----------------

__global__ void init_out_kernel(const float4* __restrict__ ent, const float4* __restrict__ rel,
                                const int* __restrict__ timep, float4* __restrict__ out) {
    const long long NODE4 = (long long)N_NODES * MEM_DIM / 4;
    const long long TOT4  = NODE4 + 500LL * MEM_DIM / 4;
    long long i = (long long)blockIdx.x * blockDim.x + threadIdx.x;
    if (i >= TOT4) return;
    int t = *timep;
    float s = (t > 1) ? (float)t / (float)(t + 1) : 1.0f;
    float4 v = (i < NODE4) ? ent[i] : rel[i - NODE4];
    v.x *= s; v.y *= s; v.z *= s; v.w *= s;
    out[i] = v;
}

// ---------------- Kernel 2: TF32 mma.sync GEMM (cp.async 4-stage) + vector-RED scatter ----------------

__global__ void __launch_bounds__(THREADS, 1)
gemm_scatter_kernel(const float* __restrict__ nodes_emb, const float* __restrict__ rels_emb,
                    const int* __restrict__ nodes_ids, const int* __restrict__ rels_ids,
                    const float* __restrict__ W_node, const float* __restrict__ b_node,
                    const float* __restrict__ W_rel, const float* __restrict__ b_rel,
                    const int* __restrict__ timep, float* __restrict__ out) {
    extern __shared__ char smem[];
    const uint32_t sb = smem_u32(smem);
    const int tid = threadIdx.x;
    const int lane = tid & 31;
    const int wid = tid >> 5;
    const int wm = wid & 1;      // warp row (2)  -> 64 M rows each
    const int wn = wid >> 1;     // warp col (4)  -> 64 N cols each

    const bool is_rel = (blockIdx.x >= (unsigned)(MT * NT));
    const int bid = is_rel ? (int)blockIdx.x - MT * NT : (int)blockIdx.x;
    const int tile_n = bid & (NT - 1);
    const int tile_m = bid >> 1;

    const float* Aptr = is_rel ? rels_emb : nodes_emb;
    const float* Wptr = is_rel ? W_rel : W_node;
    const float* bias = is_rel ? b_rel : b_node;
    const int*   ids  = is_rel ? rels_ids : nodes_ids;
    float* outhalf = out + (is_rel ? (size_t)N_NODES * MEM_DIM : 0);

    const float* Abase = Aptr + (size_t)(tile_m * BM) * IN_DIM;
    const float* Wbase = Wptr + (size_t)(tile_n * BN) * IN_DIM;

    // ---- cp.async slot precompute ----
    // A: 1024 16B-slots, 4/thread; B: 2048 slots, 8/thread. slot idx = j*256 + tid.
    const float* a_gp[4]; uint32_t a_st[4];
#pragma unroll
    for (int j = 0; j < 4; ++j) {
        int idx = j * THREADS + tid;
        int row = idx >> 3, k4 = idx & 7;
        a_gp[j] = Abase + (size_t)row * IN_DIM + k4 * 4;
        a_st[j] = (uint32_t)(row * 128 + ((k4 ^ (row & 7)) << 4));
    }
    const float* b_gp[8]; uint32_t b_st[8];
#pragma unroll
    for (int j = 0; j < 8; ++j) {
        int idx = j * THREADS + tid;
        int row = idx >> 3, k4 = idx & 7;
        b_gp[j] = Wbase + (size_t)row * IN_DIM + k4 * 4;
        b_st[j] = (uint32_t)(SA_BYTES + row * 128 + ((k4 ^ (row & 7)) << 4));
    }

    auto issue_chunk = [&](int kc) {   // always commits (empty groups keep wait arithmetic uniform)
        if (kc < KC) {
            const int koff = kc * BK;
            const uint32_t stg = sb + (uint32_t)(kc & (STAGES - 1)) * STAGE_BYTES;
#pragma unroll
            for (int j = 0; j < 4; ++j) cp_async16(stg + a_st[j], a_gp[j] + koff);
#pragma unroll
            for (int j = 0; j < 8; ++j) cp_async16(stg + b_st[j], b_gp[j] + koff);
        }
        cp_commit();
    };

    // ---- ldmatrix address precompute (same mapping as the validated R4 kernel) ----
    const int a_khi = lane >> 4;
    uint32_t a_row128[4]; int a_r7[4];
#pragma unroll
    for (int mt = 0; mt < 4; ++mt) {
        int row = wm * 64 + mt * 16 + (lane & 7) + ((lane >> 3) & 1) * 8;
        a_row128[mt] = (uint32_t)(row * 128);
        a_r7[mt] = row & 7;
    }
    const int b_khi = (lane >> 3) & 1;
    uint32_t b_row128[4]; int b_r7[4];
#pragma unroll
    for (int np = 0; np < 4; ++np) {
        int row = wn * 64 + np * 16 + (lane & 7) + ((lane >> 4) & 1) * 8;
        b_row128[np] = (uint32_t)(SA_BYTES + row * 128);
        b_r7[np] = row & 7;
    }

    float C[4][8][4];
#pragma unroll
    for (int mt = 0; mt < 4; ++mt)
#pragma unroll
        for (int nt = 0; nt < 8; ++nt)
#pragma unroll
            for (int v = 0; v < 4; ++v) C[mt][nt][v] = 0.0f;

    // ---- prologue: stages 0..2 in flight ----
    issue_chunk(0);
    issue_chunk(1);
    issue_chunk(2);

    // ---- main loop ----
    for (int kc = 0; kc < KC; ++kc) {
        cp_wait2();          // chunk kc's group complete (<=2 newer groups outstanding)
        __syncthreads();     // all warps: data visible; stage (kc+3)%4 fully consumed (read at kc-1)
        issue_chunk(kc + 3); // fire-and-forget, ~3 chunks of lead time

        const uint32_t cur = sb + (uint32_t)(kc & (STAGES - 1)) * STAGE_BYTES;
#pragma unroll
        for (int ks = 0; ks < 4; ++ks) {
            uint32_t afr[4][4];
#pragma unroll
            for (int mt = 0; mt < 4; ++mt) {
                uint32_t addr = cur + a_row128[mt] + (uint32_t)(((2 * ks + a_khi) ^ a_r7[mt]) << 4);
                ldsm_x4(afr[mt], addr);
#pragma unroll
                for (int v = 0; v < 4; ++v) afr[mt][v] = f2tf32(afr[mt][v]);
            }
#pragma unroll
            for (int np = 0; np < 4; ++np) {
                uint32_t bfr[4];
                uint32_t addr = cur + b_row128[np] + (uint32_t)(((2 * ks + b_khi) ^ b_r7[np]) << 4);
                ldsm_x4(bfr, addr);
#pragma unroll
                for (int v = 0; v < 4; ++v) bfr[v] = f2tf32(bfr[v]);
#pragma unroll
                for (int mt = 0; mt < 4; ++mt) {
                    mma_tf32(C[mt][2 * np],     afr[mt], bfr);
                    mma_tf32(C[mt][2 * np + 1], afr[mt], bfr + 2);
                }
            }
        }
        __syncthreads();     // done reading stage kc%4 before iteration kc+1 overwrites stage (kc+4)%4
    }

    // ---- epilogue: out[id[m]] += (C + bias) / (t+1), vector RED scatter (v2.f32) ----
    const int t = *timep;
    const float inv = 1.0f / (float)(t + 1);
    const int g = lane >> 2;
    const int tg = lane & 3;

    float* p[8];
#pragma unroll
    for (int mt = 0; mt < 4; ++mt) {
        int r0 = tile_m * BM + wm * 64 + mt * 16 + g;
        p[2 * mt]     = outhalf + (size_t)ids[r0] * MEM_DIM;
        p[2 * mt + 1] = outhalf + (size_t)ids[r0 + 8] * MEM_DIM;
    }
#pragma unroll
    for (int nt = 0; nt < 8; ++nt) {
        const int c = tile_n * BN + wn * 64 + nt * 8 + tg * 2;
        const float2 bv = *reinterpret_cast<const float2*>(bias + c);
#pragma unroll
        for (int mt = 0; mt < 4; ++mt) {
            red_add_v2(p[2 * mt] + c,     (C[mt][nt][0] + bv.x) * inv, (C[mt][nt][1] + bv.y) * inv);
            red_add_v2(p[2 * mt + 1] + c, (C[mt][nt][2] + bv.x) * inv, (C[mt][nt][3] + bv.y) * inv);
        }
    }
}

// ---------------- launch ----------------

extern "C" void kernel_launch(void* const* d_in, const int* in_sizes, int n_in,
                              void* d_out, int out_size) {
    const float* nodes_emb = (const float*)d_in[0];
    const float* rels_emb  = (const float*)d_in[1];
    const int*   nodes_ids = (const int*)d_in[2];
    const int*   rels_ids  = (const int*)d_in[3];
    const float* ent_mem   = (const float*)d_in[4];
    const float* rel_mem   = (const float*)d_in[5];
    const float* W_node    = (const float*)d_in[6];
    const float* b_node    = (const float*)d_in[7];
    const float* W_rel     = (const float*)d_in[8];
    const float* b_rel     = (const float*)d_in[9];
    const int*   timep     = (const int*)d_in[10];
    float* out = (float*)d_out;

    static bool attr_set = false;
    if (!attr_set) {
        cudaFuncSetAttribute(gemm_scatter_kernel,
                             cudaFuncAttributeMaxDynamicSharedMemorySize, SMEM_BYTES);
        attr_set = true;
    }

    // 1) out = scaled concat of memories
    const long long TOT4 = ((long long)N_NODES * MEM_DIM + 500LL * MEM_DIM) / 4;
    const int blocks = (int)((TOT4 + 255) / 256);
    init_out_kernel<<<blocks, 256>>>((const float4*)ent_mem, (const float4*)rel_mem, timep,
                                     (float4*)out);

    // 2) TF32 GEMM + scatter: nodes half then rels half in one grid
    gemm_scatter_kernel<<<2 * MT * NT, THREADS, SMEM_BYTES>>>(
        nodes_emb, rels_emb, nodes_ids, rels_ids,
        W_node, b_node, W_rel, b_rel, timep, out);
}

// round 12
// speedup vs baseline: 1.7957x; 1.0572x over previous
#include <cuda_runtime.h>
#include <cstdint>
#include <cstddef>

#define DI __device__ __forceinline__

namespace {
constexpr int IN_DIM  = 1024;
constexpr int MEM_DIM = 512;
constexpr int N_NODES = 100000;
constexpr int BATCH   = 65536;

constexpr int BM = 128, BN = 256, BK = 64;
constexpr int MT = BATCH / BM;     // 512
constexpr int NT = MEM_DIM / BN;   // 2
constexpr int KC = IN_DIM / BK;    // 16
constexpr int THREADS = 256;       // 8 warps: 2 (M) x 4 (N), warp tile 64x64
constexpr int STAGES = 2;

// smem per stage: A[128 rows][256B] + B[256 rows][256B]; a row = 64 fp32 (one BK chunk),
// 16B units XOR-swizzled by (row&7) for conflict-free ldmatrix (XOR touches low 3 unit bits only).
constexpr int SA_BYTES    = BM * 256;               // 32 KB
constexpr int SB_BYTES    = BN * 256;               // 64 KB
constexpr int STAGE_BYTES = SA_BYTES + SB_BYTES;    // 96 KB
constexpr int SMEM_BYTES  = STAGES * STAGE_BYTES;   // 192 KB
}  // namespace

// ---------------- base-ISA helpers (NO tcgen05 — target is plain sm_103) ----------------

DI uint32_t smem_u32(const void* p) {
    uint32_t a;
    asm("{ .reg .u64 t; cvta.to.shared.u64 t, %1; cvt.u32.u64 %0, t; }" : "=r"(a) : "l"(p));
    return a;
}

DI uint32_t f2tf32(uint32_t fbits) {   // round-to-nearest tf32 on raw fp32 bits
    uint32_t r;
    asm("cvt.rna.tf32.f32 %0, %1;" : "=r"(r) : "r"(fbits));
    return r;
}

DI void ldsm_x4(uint32_t* r, uint32_t addr) {
    asm volatile("ldmatrix.sync.aligned.m8n8.x4.shared.b16 {%0,%1,%2,%3}, [%4];"
                 : "=r"(r[0]), "=r"(r[1]), "=r"(r[2]), "=r"(r[3]) : "r"(addr));
}

DI void mma_tf32(float* c, const uint32_t* a, const uint32_t* b) {
    asm volatile(
        "mma.sync.aligned.m16n8k8.row.col.f32.tf32.tf32.f32 "
        "{%0,%1,%2,%3}, {%4,%5,%6,%7}, {%8,%9}, {%0,%1,%2,%3};"
        : "+f"(c[0]), "+f"(c[1]), "+f"(c[2]), "+f"(c[3])
        : "r"(a[0]), "r"(a[1]), "r"(a[2]), "r"(a[3]), "r"(b[0]), "r"(b[1]));
}

DI void cp_async16(uint32_t smem_addr, const void* gptr) {
    asm volatile("cp.async.cg.shared.global [%0], [%1], 16;"
                 :: "r"(smem_addr), "l"(gptr));
}
DI void cp_commit() { asm volatile("cp.async.commit_group;"); }
DI void cp_wait1()  { asm volatile("cp.async.wait_group 1;"); }

DI void red_add_v2(float* gaddr, float x, float y) {   // vector reduction, no return (sm_90+)
    asm volatile("red.global.add.v2.f32 [%0], {%1, %2};"
                 :: "l"(gaddr), "f"(x), "f"(y) : "memory");
}

// ---------------- Kernel 1: out = concat(entity_mem, rel_mem) * (t>1 ? t/(t+1) : 1) ----------------

__global__ void init_out_kernel(const float4* __restrict__ ent, const float4* __restrict__ rel,
                                const int* __restrict__ timep, float4* __restrict__ out) {
    const long long NODE4 = (long long)N_NODES * MEM_DIM / 4;
    const long long TOT4  = NODE4 + 500LL * MEM_DIM / 4;
    long long i = (long long)blockIdx.x * blockDim.x + threadIdx.x;
    if (i >= TOT4) return;
    int t = *timep;
    float s = (t > 1) ? (float)t / (float)(t + 1) : 1.0f;
    float4 v = (i < NODE4) ? ent[i] : rel[i - NODE4];
    v.x *= s; v.y *= s; v.z *= s; v.w *= s;
    out[i] = v;
}

// ---------------- Kernel 2: TF32 mma.sync GEMM (cp.async 2-stage, BK=64) + vector-RED scatter ----------------

__global__ void __launch_bounds__(THREADS, 1)
gemm_scatter_kernel(const float* __restrict__ nodes_emb, const float* __restrict__ rels_emb,
                    const int* __restrict__ nodes_ids, const int* __restrict__ rels_ids,
                    const float* __restrict__ W_node, const float* __restrict__ b_node,
                    const float* __restrict__ W_rel, const float* __restrict__ b_rel,
                    const int* __restrict__ timep, float* __restrict__ out) {
    extern __shared__ char smem[];
    const uint32_t sb = smem_u32(smem);
    const int tid = threadIdx.x;
    const int lane = tid & 31;
    const int wid = tid >> 5;
    const int wm = wid & 1;      // warp row (2)  -> 64 M rows each
    const int wn = wid >> 1;     // warp col (4)  -> 64 N cols each

    const bool is_rel = (blockIdx.x >= (unsigned)(MT * NT));
    const int bid = is_rel ? (int)blockIdx.x - MT * NT : (int)blockIdx.x;
    const int tile_n = bid & (NT - 1);
    const int tile_m = bid >> 1;

    const float* Aptr = is_rel ? rels_emb : nodes_emb;
    const float* Wptr = is_rel ? W_rel : W_node;
    const float* bias = is_rel ? b_rel : b_node;
    const int*   ids  = is_rel ? rels_ids : nodes_ids;
    float* outhalf = out + (is_rel ? (size_t)N_NODES * MEM_DIM : 0);

    const float* Abase = Aptr + (size_t)(tile_m * BM) * IN_DIM;
    const float* Wbase = Wptr + (size_t)(tile_n * BN) * IN_DIM;

    // ---- cp.async slots: 16 16B-slots per 256B row; k4 = tid&15 is slot-invariant ----
    // slot j covers row (tid>>4) + 16*j; (row & 7) is j-invariant -> scalar base + strides.
    const int  row0 = tid >> 4;                       // 0..15
    const int  k4   = tid & 15;                       // 0..15
    const uint32_t go0 = (uint32_t)(row0 * IN_DIM + k4 * 4);
    const uint32_t st0 = (uint32_t)(row0 * 256 + ((k4 ^ (row0 & 7)) << 4));

    auto issue_chunk = [&](int kc) {   // always commits (uniform wait arithmetic)
        if (kc < KC) {
            const uint32_t go = go0 + (uint32_t)(kc * BK);
            const uint32_t stg = sb + (uint32_t)((kc & (STAGES - 1)) * STAGE_BYTES);
#pragma unroll
            for (int j = 0; j < 8; ++j)                  // A: 8 slots, stride 16 rows
                cp_async16(stg + st0 + j * 16 * 256, Abase + go + j * 16 * IN_DIM);
#pragma unroll
            for (int j = 0; j < 16; ++j)                 // B: 16 slots
                cp_async16(stg + SA_BYTES + st0 + j * 16 * 256, Wbase + go + j * 16 * IN_DIM);
        }
        cp_commit();
    };

    // ---- ldmatrix address precompute (R7 mapping, 256B row pitch) ----
    const int a_khi = lane >> 4;
    uint32_t a_rowb[4]; int a_r7[4];
#pragma unroll
    for (int mt = 0; mt < 4; ++mt) {
        int row = wm * 64 + mt * 16 + (lane & 7) + ((lane >> 3) & 1) * 8;
        a_rowb[mt] = (uint32_t)(row * 256);
        a_r7[mt] = row & 7;
    }
    const int b_khi = (lane >> 3) & 1;
    uint32_t b_rowb[4]; int b_r7[4];
#pragma unroll
    for (int np = 0; np < 4; ++np) {
        int row = wn * 64 + np * 16 + (lane & 7) + ((lane >> 4) & 1) * 8;
        b_rowb[np] = (uint32_t)(SA_BYTES + row * 256);
        b_r7[np] = row & 7;
    }

    float C[4][8][4];
#pragma unroll
    for (int mt = 0; mt < 4; ++mt)
#pragma unroll
        for (int nt = 0; nt < 8; ++nt)
#pragma unroll
            for (int v = 0; v < 4; ++v) C[mt][nt][v] = 0.0f;

    // ---- prologue: 2 chunks in flight ----
    issue_chunk(0);
    issue_chunk(1);

    // ---- main loop: 16 chunks, 8 ksteps each (R7 inner body, 256B pitch) ----
    for (int kc = 0; kc < KC; ++kc) {
        cp_wait1();          // chunk kc complete (chunk kc+1 still outstanding)
        __syncthreads();     // data visible to all warps

        const uint32_t cur = sb + (uint32_t)((kc & (STAGES - 1)) * STAGE_BYTES);
#pragma unroll
        for (int ks = 0; ks < 8; ++ks) {
            uint32_t afr[4][4];
#pragma unroll
            for (int mt = 0; mt < 4; ++mt) {
                uint32_t addr = cur + a_rowb[mt] + (uint32_t)(((2 * ks + a_khi) ^ a_r7[mt]) << 4);
                ldsm_x4(afr[mt], addr);
#pragma unroll
                for (int v = 0; v < 4; ++v) afr[mt][v] = f2tf32(afr[mt][v]);
            }
#pragma unroll
            for (int np = 0; np < 4; ++np) {
                uint32_t bfr[4];
                uint32_t addr = cur + b_rowb[np] + (uint32_t)(((2 * ks + b_khi) ^ b_r7[np]) << 4);
                ldsm_x4(bfr, addr);
#pragma unroll
                for (int v = 0; v < 4; ++v) bfr[v] = f2tf32(bfr[v]);
#pragma unroll
                for (int mt = 0; mt < 4; ++mt) {
                    mma_tf32(C[mt][2 * np],     afr[mt], bfr);
                    mma_tf32(C[mt][2 * np + 1], afr[mt], bfr + 2);
                }
            }
        }
        __syncthreads();     // all warps done reading stage kc&1 before refilling it
        issue_chunk(kc + 2); // writes stage kc&1
    }

    // ---- epilogue: out[id[m]] += (C + bias) / (t+1), vector RED scatter (v2.f32) ----
    const int t = *timep;
    const float inv = 1.0f / (float)(t + 1);
    const int g = lane >> 2;
    const int tg = lane & 3;

    float* p[8];
#pragma unroll
    for (int mt = 0; mt < 4; ++mt) {
        int r0 = tile_m * BM + wm * 64 + mt * 16 + g;
        p[2 * mt]     = outhalf + (size_t)ids[r0] * MEM_DIM;
        p[2 * mt + 1] = outhalf + (size_t)ids[r0 + 8] * MEM_DIM;
    }
#pragma unroll
    for (int nt = 0; nt < 8; ++nt) {
        const int c = tile_n * BN + wn * 64 + nt * 8 + tg * 2;
        const float2 bv = *reinterpret_cast<const float2*>(bias + c);
#pragma unroll
        for (int mt = 0; mt < 4; ++mt) {
            red_add_v2(p[2 * mt] + c,     (C[mt][nt][0] + bv.x) * inv, (C[mt][nt][1] + bv.y) * inv);
            red_add_v2(p[2 * mt + 1] + c, (C[mt][nt][2] + bv.x) * inv, (C[mt][nt][3] + bv.y) * inv);
        }
    }
}

// ---------------- launch ----------------

extern "C" void kernel_launch(void* const* d_in, const int* in_sizes, int n_in,
                              void* d_out, int out_size) {
    const float* nodes_emb = (const float*)d_in[0];
    const float* rels_emb  = (const float*)d_in[1];
    const int*   nodes_ids = (const int*)d_in[2];
    const int*   rels_ids  = (const int*)d_in[3];
    const float* ent_mem   = (const float*)d_in[4];
    const float* rel_mem   = (const float*)d_in[5];
    const float* W_node    = (const float*)d_in[6];
    const float* b_node    = (const float*)d_in[7];
    const float* W_rel     = (const float*)d_in[8];
    const float* b_rel     = (const float*)d_in[9];
    const int*   timep     = (const int*)d_in[10];
    float* out = (float*)d_out;

    static bool attr_set = false;
    if (!attr_set) {
        cudaFuncSetAttribute(gemm_scatter_kernel,
                             cudaFuncAttributeMaxDynamicSharedMemorySize, SMEM_BYTES);
        attr_set = true;
    }

    // 1) out = scaled concat of memories
    const long long TOT4 = ((long long)N_NODES * MEM_DIM + 500LL * MEM_DIM) / 4;
    const int blocks = (int)((TOT4 + 255) / 256);
    init_out_kernel<<<blocks, 256>>>((const float4*)ent_mem, (const float4*)rel_mem, timep,
                                     (float4*)out);

    // 2) TF32 GEMM + scatter: nodes half then rels half in one grid
    gemm_scatter_kernel<<<2 * MT * NT, THREADS, SMEM_BYTES>>>(
        nodes_emb, rels_emb, nodes_ids, rels_ids,
        W_node, b_node, W_rel, b_rel, timep, out);
}